// round 10
// baseline (speedup 1.0000x reference)
#include <cuda_runtime.h>
#include <stdint.h>

// labels[b,l,i] = argmin_j ( tn[b,l,i] - cbn[i,j] )
//              = argmax_j cbn[i,j]            (tn constant over argmin axis j)
//              = argmax_j codebook[i,j]       (cbn = positive-scale affine of codebook)
// => output (float32) = per-row argmax of the 64x64 codebook, tiled B*L = 16384x.
//
// TERMINAL (R10 = R9 unchanged, confirmation re-bench):
// Campaign: 21.2us (naive fused) -> 10.3 (2-kernel) -> 6.1 (1-kernel, registerized
// argmax). Floor analysis: store-only kernel bodies measure 4.64us; identical-work
// bodies scatter +-0.15us; bench scatters +-0.5us. All pipes <11% -> launch/ramp
// floor, not throughput. Remaining levers (barrier removal, key narrowing,
// grid/block resizing) all cost more than they save or risk tie-break correctness.

static constexpr int QDIM    = 64;
static constexpr int TOTAL4  = (8 * 2048 * 64) / 4;   // 262144 float4 (4 MB)
static constexpr int NBLK    = 128;
static constexpr int PER_THR = TOTAL4 / (NBLK * 256); // 8 float4 per thread

// Monotone key: order-preserving f32 bits in [63:6], (63-j) in [5:0].
// u64-max => max value; among equal values, larger (63-j) => SMALLER j,
// i.e. first-index tie-break, matching jnp.argmin on (s - c_j).
__device__ __forceinline__ unsigned long long mono_key(float v, int j) {
    uint32_t u = __float_as_uint(v);
    u ^= (uint32_t)((int32_t)u >> 31) | 0x80000000u;   // ordered-uint transform
    return ((unsigned long long)u << 6) | (unsigned long long)(63 - j);
}

__device__ __forceinline__ unsigned long long kmax(unsigned long long a,
                                                   unsigned long long b) {
    return a > b ? a : b;
}

__global__ __launch_bounds__(256) void bestrq_final_kernel(
    const float4* __restrict__ cb4,       // codebook (64,64) as 1024 float4
    float4* __restrict__ out4)            // 262144 float4
{
    __shared__ alignas(16) float s_lbl[QDIM];   // float labels, float4-readable

    const int t    = threadIdx.x;
    const int row  = t >> 2;              // 0..63  (4 threads per row)
    const int part = t & 3;               // 0..3   (16 elements each)

    // ---- Load this thread's 16 row elements (4 independent LDG.128) ----
    const float4* p = cb4 + row * 16 + part * 4;
    float4 a = p[0], b = p[1], c = p[2], d = p[3];

    // Hoist the store base: post-barrier tail = LDS.128 + 8 STG only.
    const int base = blockIdx.x * (256 * PER_THR) + t;

    // ---- In-register argmax over 16 elements via monotone keys ----
    const int bj = part * 16;
    unsigned long long k;
    k =      kmax(kmax(mono_key(a.x, bj + 0), mono_key(a.y, bj + 1)),
                  kmax(mono_key(a.z, bj + 2), mono_key(a.w, bj + 3)));
    k = kmax(k, kmax(kmax(mono_key(b.x, bj + 4), mono_key(b.y, bj + 5)),
                     kmax(mono_key(b.z, bj + 6), mono_key(b.w, bj + 7))));
    k = kmax(k, kmax(kmax(mono_key(c.x, bj + 8), mono_key(c.y, bj + 9)),
                     kmax(mono_key(c.z, bj + 10), mono_key(c.w, bj + 11))));
    k = kmax(k, kmax(kmax(mono_key(d.x, bj + 12), mono_key(d.y, bj + 13)),
                     kmax(mono_key(d.z, bj + 14), mono_key(d.w, bj + 15))));

    // ---- Reduce across the 4 lanes of this row ----
    k = kmax(k, __shfl_xor_sync(0xFFFFFFFFu, k, 1));
    k = kmax(k, __shfl_xor_sync(0xFFFFFFFFu, k, 2));

    // All 4 lanes hold the identical reduced key: unpredicated same-value STS
    // to the same address (one lane wins; no divergent branch before the bar).
    s_lbl[row] = (float)(63 - (int)(k & 63));
    __syncthreads();                      // the ONLY block sync

    // ---- Read this thread's pattern slot directly (aligned LDS.128) ----
    // Slot (t & 15) = rows 4*(t&15)..+3. All store offsets below are multiples
    // of 16 float4 (one 64-label period), so the slot depends only on t.
    const float4 v = *reinterpret_cast<const float4*>(&s_lbl[4 * (t & 15)]);

#pragma unroll
    for (int kk = 0; kk < PER_THR; ++kk) {
        out4[base + kk * 256] = v;
    }
}

extern "C" void kernel_launch(void* const* d_in, const int* in_sizes, int n_in,
                              void* d_out, int out_size)
{
    (void)out_size;

    // Codebook selection by size (elements: 4096; bytes fallback: 16384).
    const float* codebook = nullptr;
    int max_sz = 0;
    for (int i = 0; i < n_in; ++i) if (in_sizes[i] > max_sz) max_sz = in_sizes[i];
    for (int i = 0; i < n_in; ++i) {
        if (in_sizes[i] == QDIM * QDIM) codebook = (const float*)d_in[i];
    }
    if (!codebook && max_sz > 8 * 1024 * 1024) {
        for (int i = 0; i < n_in; ++i) {
            if (in_sizes[i] == QDIM * QDIM * 4) codebook = (const float*)d_in[i];
        }
    }
    if (!codebook) codebook = (const float*)d_in[n_in - 1];

    bestrq_final_kernel<<<NBLK, 256>>>((const float4*)codebook, (float4*)d_out);
}

// round 11
// speedup vs baseline: 1.0052x; 1.0052x over previous
#include <cuda_runtime.h>
#include <stdint.h>

// labels[b,l,i] = argmin_j ( tn[b,l,i] - cbn[i,j] )
//              = argmax_j cbn[i,j]            (tn constant over argmin axis j)
//              = argmax_j codebook[i,j]       (cbn = positive-scale affine of codebook)
// => output (float32) = per-row argmax of the 64x64 codebook, tiled B*L = 16384x.
//
// R10 post-mortem: model confirmed (bench 6.14/6.18 back-to-back; body 4.93;
// floor ~4.6us; all pipes <11%). R11 final micro-lever: Blackwell 256-bit
// stores (st.global.v8.f32) halve the store tail's STG count (8x128b -> 4x256b).
// Argmax math and tie-break untouched.

static constexpr int QDIM    = 64;
static constexpr int TOTAL8  = (8 * 2048 * 64) / 8;   // 131072 float8 chunks (4 MB)
static constexpr int NBLK    = 128;
static constexpr int PER_THR = TOTAL8 / (NBLK * 256); // 4 x 32B stores per thread

// Monotone key: order-preserving f32 bits in [63:6], (63-j) in [5:0].
// u64-max => max value; among equal values, larger (63-j) => SMALLER j,
// i.e. first-index tie-break, matching jnp.argmin on (s - c_j).
__device__ __forceinline__ unsigned long long mono_key(float v, int j) {
    uint32_t u = __float_as_uint(v);
    u ^= (uint32_t)((int32_t)u >> 31) | 0x80000000u;   // ordered-uint transform
    return ((unsigned long long)u << 6) | (unsigned long long)(63 - j);
}

__device__ __forceinline__ unsigned long long kmax(unsigned long long a,
                                                   unsigned long long b) {
    return a > b ? a : b;
}

// 256-bit store (sm_100a+): one STG.256 of 8 consecutive f32.
__device__ __forceinline__ void stg256(float* p, float4 lo, float4 hi) {
    asm volatile(
        "st.global.v8.f32 [%0], {%1, %2, %3, %4, %5, %6, %7, %8};"
        :: "l"(p),
           "f"(lo.x), "f"(lo.y), "f"(lo.z), "f"(lo.w),
           "f"(hi.x), "f"(hi.y), "f"(hi.z), "f"(hi.w)
        : "memory");
}

__global__ __launch_bounds__(256) void bestrq_final_v8_kernel(
    const float4* __restrict__ cb4,       // codebook (64,64) as 1024 float4
    float* __restrict__ out)              // 1048576 f32 (32B-aligned harness buffer)
{
    __shared__ alignas(32) float s_lbl[QDIM];   // float labels, 32B-readable

    const int t    = threadIdx.x;
    const int row  = t >> 2;              // 0..63  (4 threads per row)
    const int part = t & 3;               // 0..3   (16 elements each)

    // ---- Load this thread's 16 row elements (4 independent LDG.128) ----
    const float4* p = cb4 + row * 16 + part * 4;
    float4 a = p[0], b = p[1], c = p[2], d = p[3];

    // Hoist the store base: post-barrier tail = 2x LDS.128 + 4x STG.256 only.
    // base in float8 units; each float8 = 8 f32 = 32 B.
    const int base8 = blockIdx.x * (256 * PER_THR) + t;

    // ---- In-register argmax over 16 elements via monotone keys ----
    const int bj = part * 16;
    unsigned long long k;
    k =      kmax(kmax(mono_key(a.x, bj + 0), mono_key(a.y, bj + 1)),
                  kmax(mono_key(a.z, bj + 2), mono_key(a.w, bj + 3)));
    k = kmax(k, kmax(kmax(mono_key(b.x, bj + 4), mono_key(b.y, bj + 5)),
                     kmax(mono_key(b.z, bj + 6), mono_key(b.w, bj + 7))));
    k = kmax(k, kmax(kmax(mono_key(c.x, bj + 8), mono_key(c.y, bj + 9)),
                     kmax(mono_key(c.z, bj + 10), mono_key(c.w, bj + 11))));
    k = kmax(k, kmax(kmax(mono_key(d.x, bj + 12), mono_key(d.y, bj + 13)),
                     kmax(mono_key(d.z, bj + 14), mono_key(d.w, bj + 15))));

    // ---- Reduce across the 4 lanes of this row ----
    k = kmax(k, __shfl_xor_sync(0xFFFFFFFFu, k, 1));
    k = kmax(k, __shfl_xor_sync(0xFFFFFFFFu, k, 2));

    // All 4 lanes hold the identical reduced key: unpredicated same-value STS.
    s_lbl[row] = (float)(63 - (int)(k & 63));
    __syncthreads();                      // the ONLY block sync

    // ---- This thread's 32 B pattern slot: rows 8*(t&7) .. +7 ----
    // Pattern period = 64 floats = 8 float8 slots; all store offsets below are
    // multiples of 8 float8 (base8 stride 256, block stride 1024), so the slot
    // depends only on (t & 7).
    const float4* sl = reinterpret_cast<const float4*>(&s_lbl[8 * (t & 7)]);
    const float4 lo = sl[0], hi = sl[1];

#pragma unroll
    for (int kk = 0; kk < PER_THR; ++kk) {
        stg256(out + (size_t)(base8 + kk * 256) * 8, lo, hi);
    }
}

extern "C" void kernel_launch(void* const* d_in, const int* in_sizes, int n_in,
                              void* d_out, int out_size)
{
    (void)out_size;

    // Codebook selection by size (elements: 4096; bytes fallback: 16384).
    const float* codebook = nullptr;
    int max_sz = 0;
    for (int i = 0; i < n_in; ++i) if (in_sizes[i] > max_sz) max_sz = in_sizes[i];
    for (int i = 0; i < n_in; ++i) {
        if (in_sizes[i] == QDIM * QDIM) codebook = (const float*)d_in[i];
    }
    if (!codebook && max_sz > 8 * 1024 * 1024) {
        for (int i = 0; i < n_in; ++i) {
            if (in_sizes[i] == QDIM * QDIM * 4) codebook = (const float*)d_in[i];
        }
    }
    if (!codebook) codebook = (const float*)d_in[n_in - 1];

    bestrq_final_v8_kernel<<<NBLK, 256>>>((const float4*)codebook, (float*)d_out);
}